// round 13
// baseline (speedup 1.0000x reference)
#include <cuda_runtime.h>
#include <math.h>

#define D 128
#define E_TOTAL 640000
#define NMAX 40000
#define NPAD (NMAX + 1024)

static const int NS[10] = {40000,32000,25600,20480,16384,13108,10487,8390,6712,5370};
static const int KS[10] = {32000,25600,20480,16384,13108,10487,8390,6712,5370,4296};
static const int NT[10] = {40,32,25,20,16,13,11,9,7,6};  // (NS+1023)/1024

// ---------------- device scratch ----------------
__device__ float g_h2 [NMAX*D];
__device__ float g_hw [NMAX*D];
__device__ float g_hv [NMAX*D];
__device__ float g_score[NMAX];
__device__ float g_dinv [NMAX];
__device__ __align__(16) int g_degi[NPAD];
__device__ int   g_remap[NMAX];
__device__ int   g_sel  [NMAX];
__device__ int   g_off  [NMAX+1];
__device__ int   g_cur  [NMAX];
__device__ int   g_csr  [E_TOTAL];
__device__ int2  g_edges[2][E_TOTAL];
__device__ int   g_ecnt[11];
__device__ int   g_tilesum[64];
__device__ int   g_tilepref[64];
__device__ unsigned g_hist[3][65536];   // zero at load; k_aggtopk restores zeros after use
__device__ unsigned g_coarse[3][1024];
__device__ unsigned g_selcnt;
__device__ unsigned g_doneB;
__device__ unsigned g_doneC;
__device__ unsigned g_barArr;
__device__ volatile unsigned g_barGen;
__device__ unsigned g_umax[D];
__device__ float g_colsum[D];
__device__ float g_reads[2560];
__device__ float g_z1[1280];
__device__ float g_bnsc[10*D];
__device__ float g_bnsh[10*D];
__device__ float g_pnorm[10];

// ---------------- helpers ----------------
__device__ __forceinline__ unsigned fmap(float f) {
    unsigned b = __float_as_uint(f);
    return (b & 0x80000000u) ? ~b : (b | 0x80000000u);
}
__device__ __forceinline__ float funmap(unsigned u) {
    unsigned b = (u & 0x80000000u) ? (u ^ 0x80000000u) : ~u;
    return __uint_as_float(b);
}
// 48-bit key: score (32) | inverted index (16). larger == better; ties -> smaller index.
__device__ __forceinline__ unsigned long long make_key(float s, int i) {
    return (((unsigned long long)fmap(s)) << 16) | (unsigned)(0xFFFFu - (unsigned)i);
}

__device__ __forceinline__ void mma_tf32(float* c, const unsigned* a, unsigned b0, unsigned b1) {
    asm volatile(
        "mma.sync.aligned.m16n8k8.row.col.f32.tf32.tf32.f32 "
        "{%0,%1,%2,%3}, {%4,%5,%6,%7}, {%8,%9}, {%0,%1,%2,%3};\n"
        : "+f"(c[0]), "+f"(c[1]), "+f"(c[2]), "+f"(c[3])
        : "r"(a[0]), "r"(a[1]), "r"(a[2]), "r"(a[3]), "r"(b0), "r"(b1));
}

// grid barrier: safe only when ALL nb blocks are resident (single wave). Used ONLY
// by k_aggtopk, which runs alone on its stream while nothing else can occupy its SMs.
__device__ __forceinline__ void gridbar(unsigned nb) {
    __syncthreads();
    if (threadIdx.x == 0) {
        __threadfence();
        unsigned gen = g_barGen;
        if (atomicAdd(&g_barArr, 1u) == nb - 1) {
            g_barArr = 0;
            __threadfence();
            g_barGen = gen + 1;
        } else {
            while (g_barGen == gen) __nanosleep(64);
            __threadfence();
        }
    }
    __syncthreads();
}

// ---------------- init ----------------
__global__ void k_zerodeg() {
    int gid = blockIdx.x * blockDim.x + threadIdx.x;
    if (gid < NPAD) g_degi[gid] = 0;
}

__global__ void k_init(const int* __restrict__ ei) {
    int gid = blockIdx.x * blockDim.x + threadIdx.x;
    int stride = gridDim.x * blockDim.x;
    for (int i = gid; i < E_TOTAL; i += stride) {
        int d = ei[E_TOTAL + i];
        g_edges[0][i] = make_int2(ei[i], d);
        atomicAdd(&g_degi[d], 1);
    }
    if (gid == 0) g_ecnt[0] = E_TOTAL;
}

// fused BN-const precompute + pool-vector norms + z1 zero: grid 10, block 128
__global__ void k_prep(const float* __restrict__ gamma, const float* __restrict__ beta,
                       const float* __restrict__ mean, const float* __restrict__ var,
                       const float* __restrict__ p) {
    int L = blockIdx.x;
    int t = threadIdx.x;
    int idx = L * 128 + t;
    float sc = gamma[idx] / sqrtf(var[idx] + 1e-5f);
    g_bnsc[idx] = sc;
    g_bnsh[idx] = beta[idx] - mean[idx] * sc;
    g_z1[idx] = 0.f;
    __shared__ float sm[128];
    float v = p[idx];
    sm[t] = v * v;
    __syncthreads();
    for (int s = 64; s > 0; s >>= 1) {
        if (t < s) sm[t] += sm[t + s];
        __syncthreads();
    }
    if (t == 0) g_pnorm[L] = sqrtf(sm[0]);
}

// ---------------- side-stream chain ----------------
// merged: blocks [0, rb) do column max/sum -> g_reads; blocks [rb, ..) remap+compact edges
__global__ void __launch_bounds__(128) k_side1(int L, int k, int ebuf, float invk, int rb) {
    int c = threadIdx.x;
    if ((int)blockIdx.x < rb) {
        // ---- reads reduce ----
        int r0 = blockIdx.x * 64;
        float lmax = __int_as_float(0xff800000);
        float lsum = 0.f;
        int rend = r0 + 64; if (rend > k) rend = k;
        for (int r = r0; r < rend; r++) {
            int i = g_sel[r];
            float v = g_h2[(size_t)i * 128 + c] * g_score[i];
            lmax = fmaxf(lmax, v);
            lsum += v;
        }
        atomicMax(&g_umax[c], fmap(lmax));
        atomicAdd(&g_colsum[c], lsum);
        __threadfence();
        __shared__ int lastb;
        if (c == 0) {
            unsigned v = atomicAdd(&g_doneB, 1u);
            lastb = (v == (unsigned)rb - 1);
            if (lastb) g_doneB = 0u;
        }
        __syncthreads();
        if (lastb) {
            g_reads[L * 256 + c] = funmap(g_umax[c]);
            g_reads[L * 256 + 128 + c] = g_colsum[c] * invk;
        }
    } else {
        // ---- edge remap + compaction + next-layer degrees (warp-aggregated) ----
        int bid = blockIdx.x - rb;
        int gid = bid * 128 + c;
        int stride = ((int)gridDim.x - rb) * 128;
        int lane = c & 31;
        int cnt = g_ecnt[L];
        const int2* Ein = g_edges[ebuf];
        int2* Eout = g_edges[ebuf ^ 1];
        int iters = (cnt + stride - 1) / stride;
        for (int it = 0; it < iters; it++) {
            int i = gid + it * stride;
            int ns = -1, nd = -1;
            if (i < cnt) {
                int2 e = Ein[i];
                ns = g_remap[e.x];
                nd = g_remap[e.y];
            }
            bool keep = (ns >= 0) && (nd >= 0);
            unsigned bm = __ballot_sync(0xFFFFFFFFu, keep);
            if (keep) {
                int leader = __ffs(bm) - 1;
                unsigned base;
                if (lane == leader) base = (unsigned)atomicAdd(&g_ecnt[L + 1], __popc(bm));
                base = __shfl_sync(bm, base, leader);
                unsigned pos = base + __popc(bm & ((1u << lane) - 1u));
                Eout[pos] = make_int2(ns, nd);
                atomicAdd(&g_degi[nd], 1);
            }
        }
    }
}

// tile degree sums + per-layer scalar zeroing; last block computes tile prefix.
__global__ void __launch_bounds__(256) k_tilesum(int L, int n, int ntiles) {
    int t = threadIdx.x;
    int bid = blockIdx.x;
    int gid = bid * 256 + t;
    if (gid < 128) { g_umax[gid] = 0u; g_colsum[gid] = 0.f; }
    if (gid == 0) { g_selcnt = 0u; g_ecnt[L + 1] = 0; }

    int base = bid * 1024 + t * 4;
    int4 dv = *(const int4*)&g_degi[base];
    int s = 0;
    if (base + 0 < n) s += dv.x;
    if (base + 1 < n) s += dv.y;
    if (base + 2 < n) s += dv.z;
    if (base + 3 < n) s += dv.w;
#pragma unroll
    for (int off = 16; off > 0; off >>= 1) s += __shfl_xor_sync(0xFFFFFFFFu, s, off);
    __shared__ int ws[8];
    if ((t & 31) == 0) ws[t >> 5] = s;
    __syncthreads();
    if (t == 0) {
        int tot = 0;
#pragma unroll
        for (int j = 0; j < 8; j++) tot += ws[j];
        g_tilesum[bid] = tot;
    }
    __threadfence();
    __shared__ int lastb;
    if (t == 0) {
        unsigned v = atomicAdd(&g_doneC, 1u);
        lastb = (v == (unsigned)ntiles - 1);
        if (lastb) g_doneC = 0u;
    }
    __syncthreads();
    if (lastb && t == 0) {
        int run = 0;
        for (int i = 0; i < ntiles; i++) { g_tilepref[i] = run; run += g_tilesum[i]; }
        g_off[n] = run;
    }
}

// expand per-tile offsets: one block per 1024-node tile
__global__ void __launch_bounds__(256) k_offsets(int n) {
    int t = threadIdx.x;
    int base = blockIdx.x * 1024 + t * 4;
    int4 dv = *(const int4*)&g_degi[base];
    int d0 = (base + 0 < n) ? dv.x : 0;
    int d1 = (base + 1 < n) ? dv.y : 0;
    int d2 = (base + 2 < n) ? dv.z : 0;
    int d3 = (base + 3 < n) ? dv.w : 0;
    int s = d0 + d1 + d2 + d3;
    int lane = t & 31, wid = t >> 5;
    int incl = s;
#pragma unroll
    for (int off = 1; off < 32; off <<= 1) {
        int v = __shfl_up_sync(0xFFFFFFFFu, incl, off);
        if (lane >= off) incl += v;
    }
    __shared__ int wsum[8], wpref[8];
    if (lane == 31) wsum[wid] = incl;
    __syncthreads();
    if (t < 8) {
        int pp = 0;
#pragma unroll
        for (int j = 0; j < 8; j++) {
            int u = wsum[j];
            if (j < t) pp += u;
        }
        wpref[t] = pp;
    }
    __syncthreads();
    int excl = incl - s + wpref[wid] + g_tilepref[blockIdx.x];
    int dd[4] = {d0, d1, d2, d3};
#pragma unroll
    for (int j = 0; j < 4; j++) {
        int idx = base + j;
        if (idx < n) {
            g_off[idx] = excl;
            g_cur[idx] = excl;
            g_dinv[idx] = (dd[j] > 0) ? (1.0f / sqrtf((float)dd[j])) : 0.f;
            excl += dd[j];
        }
    }
}

// CSR fill: 1 atomic per edge, grid-stride (addresses mostly distinct)
__global__ void k_csrfill(int L, int ebuf) {
    int gid = blockIdx.x * blockDim.x + threadIdx.x;
    int stride = gridDim.x * blockDim.x;
    int cnt = g_ecnt[L];
    const int2* E = g_edges[ebuf];
    for (int i = gid; i < cnt; i += stride) {
        int2 e = E[i];
        int pos = atomicAdd(&g_cur[e.y], 1);
        g_csr[pos] = e.x;
    }
}

// layer 0: hw = x * W1, hv = x * V1
__global__ void k_rank1(const float* __restrict__ x, const float* __restrict__ w,
                        const float* __restrict__ v, int n) {
    int gid = blockIdx.x * blockDim.x + threadIdx.x;
    int stride = gridDim.x * blockDim.x;
    const float4* w4 = (const float4*)w;
    const float4* v4 = (const float4*)v;
    float4* ow = (float4*)g_hw;
    float4* ov = (float4*)g_hv;
    for (int i = gid; i < n * 32; i += stride) {
        float xv = x[i >> 5];
        float4 wv = w4[i & 31];
        float4 vv = v4[i & 31];
        ow[i] = make_float4(xv * wv.x, xv * wv.y, xv * wv.z, xv * wv.w);
        ov[i] = make_float4(xv * vv.x, xv * vv.y, xv * vv.z, xv * vv.w);
    }
}

// ---------------- fused agg+epilogue+score + top-k (persistent, gridbar) ----------------
// warp-shuffle block suffix-scan: 4 syncthreads instead of 17
__device__ __forceinline__ void scan_pass(int pass, unsigned kr_in, unsigned* kr_out,
                                          unsigned long long* prefix, int shift) {
    __shared__ unsigned sh[256];
    __shared__ unsigned wtot[8];
    __shared__ unsigned sh_dig, sh_kr;
    int t = threadIdx.x;
    int lane = t & 31, wid = t >> 5;
    int cb0 = t * 4;
    unsigned s = 0;
#pragma unroll
    for (int q = 0; q < 4; q++) s += g_coarse[pass][cb0 + q];
    sh[t] = s;
    __syncthreads();
    unsigned v = sh[255 - t];
    unsigned incl = v;
#pragma unroll
    for (int off = 1; off < 32; off <<= 1) {
        unsigned u = __shfl_up_sync(0xFFFFFFFFu, incl, off);
        if (lane >= off) incl += u;
    }
    if (lane == 31) wtot[wid] = incl;
    __syncthreads();
    unsigned woff = 0;
#pragma unroll
    for (int j = 0; j < 8; j++)
        if (j < wid) woff += wtot[j];
    sh[t] = incl + woff;          // inclusive scan of reversed chunk sums
    __syncthreads();
    unsigned suf = sh[255 - t];   // suffix sum incl. own chunk
    unsigned above = suf - s;
    if (above < kr_in && suf >= kr_in) {   // exactly one thread
        unsigned running = above;
        for (int b = 3; b >= 0; b--) {
            unsigned c = g_coarse[pass][cb0 + b];
            if (running + c >= kr_in) {
                int fb = (cb0 + b) * 64;
                for (int d = 63; d >= 0; d--) {
                    unsigned fc = g_hist[pass][fb + d];
                    if (running + fc >= kr_in) {
                        sh_kr = kr_in - running;
                        sh_dig = (unsigned)(fb + d);
                        break;
                    }
                    running += fc;
                }
                break;
            }
            running += c;
        }
    }
    __syncthreads();
    *prefix |= ((unsigned long long)sh_dig) << shift;
    *kr_out = sh_kr;
    __syncthreads();  // protect shared reuse next pass
}

__global__ void __launch_bounds__(256) k_aggtopk(int L, int n, unsigned k, int nb,
                                                 const float* __restrict__ convb,
                                                 const float* __restrict__ pa,
                                                 const float* __restrict__ p) {
    int t = threadIdx.x;
    int lane = t & 31;

    // ===== phase A: aggregation + conv epilogue + BN + PReLU + score (grid-stride warps) =====
    {
        float a = pa[0];
        float4 cb = ((const float4*)convb)[lane];
        float4 s4 = ((const float4*)(g_bnsc + L * 128))[lane];
        float4 h4 = ((const float4*)(g_bnsh + L * 128))[lane];
        float4 p4 = ((const float4*)p)[lane];
        float pn = g_pnorm[L];
        const float4* hw4 = (const float4*)g_hw;
        int gwarp = blockIdx.x * 8 + (t >> 5);
        int nwarps = nb * 8;
        for (int node = gwarp; node < n; node += nwarps) {
            int st = g_off[node], en = g_off[node + 1];
            float dd = g_dinv[node];
            float4 acc = make_float4(0.f, 0.f, 0.f, 0.f);
            int j = st;
            for (; j + 4 <= en; j += 4) {           // unroll-4: MLP for the L2 gather
                int s0 = g_csr[j], s1 = g_csr[j + 1], s2 = g_csr[j + 2], s3 = g_csr[j + 3];
                float c0 = g_dinv[s0] * dd, c1 = g_dinv[s1] * dd;
                float c2 = g_dinv[s2] * dd, c3 = g_dinv[s3] * dd;
                float4 v0 = hw4[(size_t)s0 * 32 + lane];
                float4 v1 = hw4[(size_t)s1 * 32 + lane];
                float4 v2 = hw4[(size_t)s2 * 32 + lane];
                float4 v3 = hw4[(size_t)s3 * 32 + lane];
                acc.x += v0.x * c0 + v1.x * c1 + v2.x * c2 + v3.x * c3;
                acc.y += v0.y * c0 + v1.y * c1 + v2.y * c2 + v3.y * c3;
                acc.z += v0.z * c0 + v1.z * c1 + v2.z * c2 + v3.z * c3;
                acc.w += v0.w * c0 + v1.w * c1 + v2.w * c2 + v3.w * c3;
            }
            for (; j < en; j++) {
                int s = g_csr[j];
                float c = g_dinv[s] * dd;
                float4 v = hw4[(size_t)s * 32 + lane];
                acc.x += v.x * c; acc.y += v.y * c; acc.z += v.z * c; acc.w += v.w * c;
            }
            float4 hv = ((const float4*)g_hv)[(size_t)node * 32 + lane];
            float o[4] = {acc.x + hv.x + cb.x, acc.y + hv.y + cb.y,
                          acc.z + hv.z + cb.z, acc.w + hv.w + cb.w};
            float bs[4] = {s4.x, s4.y, s4.z, s4.w};
            float bh[4] = {h4.x, h4.y, h4.z, h4.w};
            float pv[4] = {p4.x, p4.y, p4.z, p4.w};
            float sp = 0.f;
#pragma unroll
            for (int q = 0; q < 4; q++) {
                float v = fmaxf(o[q], 0.f);
                v = v * bs[q] + bh[q];
                v = v > 0.f ? v : a * v;
                o[q] = v;
                sp += v * pv[q];
            }
            ((float4*)g_h2)[(size_t)node * 32 + lane] = make_float4(o[0], o[1], o[2], o[3]);
#pragma unroll
            for (int off = 16; off > 0; off >>= 1) sp += __shfl_xor_sync(0xFFFFFFFFu, sp, off);
            if (lane == 0) g_score[node] = tanhf(sp / pn);
        }
    }

    gridbar((unsigned)nb);   // all scores visible

    // ===== phase B: top-k radix select (warp-aggregated atomics, self-cleaning) =====
    int i = blockIdx.x * 256 + t;
    bool valid = (i < n);
    unsigned long long key = valid ? make_key(g_score[i], i) : 0ull;
    unsigned long long prefix = 0;
    unsigned kr = k;
    unsigned digits[3];
    int actmask = 0;
#pragma unroll
    for (int pass = 0; pass < 3; pass++) {
        int shift = 32 - 16 * pass;
        bool act = valid && (pass == 0 || ((key >> (shift + 16)) == (prefix >> (shift + 16))));
        unsigned digit = (unsigned)((key >> shift) & 0xFFFFull);
        unsigned am = __ballot_sync(0xFFFFFFFFu, act);
        if (act) {
            digits[pass] = digit;
            actmask |= 1 << pass;
            unsigned peers = __match_any_sync(am, digit);
            if (lane == (__ffs(peers) - 1)) {
                unsigned cnt = (unsigned)__popc(peers);
                atomicAdd(&g_hist[pass][digit], cnt);
                atomicAdd(&g_coarse[pass][digit >> 6], cnt);
            }
        }
        gridbar((unsigned)nb);
        scan_pass(pass, kr, &kr, &prefix, shift);
    }
    gridbar((unsigned)nb);  // all scans done before clearing
#pragma unroll
    for (int pass = 0; pass < 3; pass++) {
        bool a = (actmask >> pass) & 1;
        unsigned am = __ballot_sync(0xFFFFFFFFu, a);
        if (a) {
            unsigned peers = __match_any_sync(am, digits[pass]);
            if (lane == (__ffs(peers) - 1)) {
                g_hist[pass][digits[pass]] = 0u;
                g_coarse[pass][digits[pass] >> 6] = 0u;
            }
        }
    }
    if (valid) g_degi[i] = 0;  // degrees consumed; clear for next layer
    bool sel = valid && (key >= prefix);
    unsigned bm = __ballot_sync(0xFFFFFFFFu, sel);
    if (sel) {
        int leader = __ffs(bm) - 1;
        unsigned base;
        if (lane == leader) base = atomicAdd(&g_selcnt, (unsigned)__popc(bm));
        base = __shfl_sync(bm, base, leader);
        unsigned pos = base + __popc(bm & ((1u << lane) - 1u));
        g_sel[pos] = i;
        g_remap[i] = (int)pos;
    } else if (valid) {
        g_remap[i] = -1;
    }
}

// ---------------- TF32 tensor-core GEMM with indirect pooled A ----------------
// A row r = g_h2[g_sel[r]] * g_score[g_sel[r]]   (pooled output of previous layer)
#define GBK 16
__global__ void __launch_bounds__(256) k_gemm2(const float* __restrict__ W,
                                               const float* __restrict__ V, int n) {
    __shared__ float Ah[GBK][136], Al[GBK][136];
    __shared__ float Bh[GBK][136], Bl[GBK][136];
    const float* B = blockIdx.y ? V : W;
    float* out = blockIdx.y ? g_hv : g_hw;
    int tid = threadIdx.x;
    int lane = tid & 31;
    int warp = tid >> 5;
    int wm = warp >> 2;
    int wn = warp & 3;
    int group = lane >> 2;
    int tig = lane & 3;
    int row0 = blockIdx.x * 128;

    float acc[4][4][4];
#pragma unroll
    for (int mt = 0; mt < 4; mt++)
#pragma unroll
        for (int nt = 0; nt < 4; nt++)
#pragma unroll
            for (int e = 0; e < 4; e++) acc[mt][nt][e] = 0.f;

    for (int k0 = 0; k0 < 128; k0 += GBK) {
#pragma unroll
        for (int q = 0; q < 2; q++) {
            int f = tid + 256 * q;
            int m = f >> 2;
            int kq = (f & 3) * 4;
            int gr = row0 + m; if (gr >= n) gr = n - 1;
            int src = g_sel[gr];
            float sc = g_score[src];
            float4 v = *(const float4*)(g_h2 + (size_t)src * 128 + k0 + kq);
            float xs[4] = {v.x * sc, v.y * sc, v.z * sc, v.w * sc};
#pragma unroll
            for (int j = 0; j < 4; j++) {
                float xv = xs[j];
                float hf = __uint_as_float(__float_as_uint(xv) & 0xFFFFE000u);
                Ah[kq + j][m] = hf;
                Al[kq + j][m] = xv - hf;
            }
        }
#pragma unroll
        for (int q = 0; q < 2; q++) {
            int f = tid + 256 * q;
            int kk = f >> 5;
            int nq = (f & 31) * 4;
            float4 v = *(const float4*)(B + (size_t)(k0 + kk) * 128 + nq);
            float xs[4] = {v.x, v.y, v.z, v.w};
            float hi[4], lo[4];
#pragma unroll
            for (int j = 0; j < 4; j++) {
                hi[j] = __uint_as_float(__float_as_uint(xs[j]) & 0xFFFFE000u);
                lo[j] = xs[j] - hi[j];
            }
            *(float4*)&Bh[kk][nq] = make_float4(hi[0], hi[1], hi[2], hi[3]);
            *(float4*)&Bl[kk][nq] = make_float4(lo[0], lo[1], lo[2], lo[3]);
        }
        __syncthreads();
#pragma unroll
        for (int ks = 0; ks < GBK; ks += 8) {
            unsigned ah[4][4], al[4][4];
#pragma unroll
            for (int mt = 0; mt < 4; mt++) {
                int m = wm * 64 + mt * 16 + group;
                ah[mt][0] = __float_as_uint(Ah[ks + tig][m]);
                ah[mt][1] = __float_as_uint(Ah[ks + tig][m + 8]);
                ah[mt][2] = __float_as_uint(Ah[ks + tig + 4][m]);
                ah[mt][3] = __float_as_uint(Ah[ks + tig + 4][m + 8]);
                al[mt][0] = __float_as_uint(Al[ks + tig][m]);
                al[mt][1] = __float_as_uint(Al[ks + tig][m + 8]);
                al[mt][2] = __float_as_uint(Al[ks + tig + 4][m]);
                al[mt][3] = __float_as_uint(Al[ks + tig + 4][m + 8]);
            }
#pragma unroll
            for (int nt = 0; nt < 4; nt++) {
                int c = wn * 32 + nt * 8 + group;
                unsigned bh0 = __float_as_uint(Bh[ks + tig][c]);
                unsigned bh1 = __float_as_uint(Bh[ks + tig + 4][c]);
                unsigned bl0 = __float_as_uint(Bl[ks + tig][c]);
                unsigned bl1 = __float_as_uint(Bl[ks + tig + 4][c]);
#pragma unroll
                for (int mt = 0; mt < 4; mt++) {
                    mma_tf32(acc[mt][nt], ah[mt], bh0, bh1);
                    mma_tf32(acc[mt][nt], ah[mt], bl0, bl1);
                    mma_tf32(acc[mt][nt], al[mt], bh0, bh1);
                }
            }
        }
        __syncthreads();
    }

#pragma unroll
    for (int mt = 0; mt < 4; mt++) {
#pragma unroll
        for (int h = 0; h < 2; h++) {
            int r = row0 + wm * 64 + mt * 16 + group + 8 * h;
            if (r >= n) continue;
#pragma unroll
            for (int nt = 0; nt < 4; nt++) {
                int cb = wn * 32 + nt * 8 + tig * 2;
                *(float2*)(out + (size_t)r * 128 + cb) =
                    make_float2(acc[mt][nt][2 * h], acc[mt][nt][2 * h + 1]);
            }
        }
    }
}

// ---------------- MLP head ----------------
__global__ void k_lin1(const float* __restrict__ W) {
    int col = blockIdx.x * 256 + threadIdx.x;
    int r0 = blockIdx.y * 320;
    float acc = 0.f;
    for (int r = r0; r < r0 + 320; r++) acc += g_reads[r] * W[(size_t)r * 1280 + col];
    atomicAdd(&g_z1[col], acc);
}

__global__ void k_lin2(const float* __restrict__ b1, const float* __restrict__ W2,
                       const float* __restrict__ b2, const float* __restrict__ pa,
                       float* __restrict__ out) {
    int tid = threadIdx.x;
    float a = pa[0];
    float acc[8] = {0, 0, 0, 0, 0, 0, 0, 0};
    for (int i = tid; i < 1280; i += 256) {
        float v = g_z1[i] + b1[i];
        v = v > 0.f ? v : a * v;
#pragma unroll
        for (int j = 0; j < 8; j++) acc[j] += v * W2[i * 8 + j];
    }
    __shared__ float red[256][8];
#pragma unroll
    for (int j = 0; j < 8; j++) red[tid][j] = acc[j];
    __syncthreads();
    for (int s = 128; s > 0; s >>= 1) {
        if (tid < s)
#pragma unroll
            for (int j = 0; j < 8; j++) red[tid][j] += red[tid + s][j];
        __syncthreads();
    }
    if (tid == 0) {
        float z[8];
#pragma unroll
        for (int j = 0; j < 8; j++) {
            float s = red[0][j] + b2[j];
            z[j] = s > 0.f ? s : a * s;
        }
        float mn = z[0];
#pragma unroll
        for (int j = 1; j < 8; j++) mn = fminf(mn, z[j]);
#pragma unroll
        for (int j = 0; j < 8; j++) z[j] -= mn;
        float mx = z[0];
#pragma unroll
        for (int j = 1; j < 8; j++) mx = fmaxf(mx, z[j]);
#pragma unroll
        for (int j = 0; j < 8; j++) z[j] /= mx;
        float sm = 0.f;
#pragma unroll
        for (int j = 0; j < 8; j++) sm += z[j];
#pragma unroll
        for (int j = 0; j < 8; j++) out[j] = z[j] / sm;
    }
}

// ---------------- launcher ----------------
extern "C" void kernel_launch(void* const* d_in, const int* in_sizes, int n_in,
                              void* d_out, int out_size) {
    const float* x       = (const float*)d_in[0];
    const int*   ei      = (const int*)  d_in[1];
    const float* W1      = (const float*)d_in[2];
    const float* V1      = (const float*)d_in[3];
    const float* Ws      = (const float*)d_in[4];
    const float* Vs      = (const float*)d_in[5];
    const float* conv_b  = (const float*)d_in[6];
    const float* bn_g    = (const float*)d_in[7];
    const float* bn_b    = (const float*)d_in[8];
    const float* bn_m    = (const float*)d_in[9];
    const float* bn_v    = (const float*)d_in[10];
    const float* pool_p  = (const float*)d_in[11];
    const float* prelu_a = (const float*)d_in[12];
    const float* lin1_w  = (const float*)d_in[13];
    const float* lin1_b  = (const float*)d_in[14];
    const float* lin2_w  = (const float*)d_in[15];
    const float* lin2_b  = (const float*)d_in[16];
    float* out = (float*)d_out;

    // side stream + fork/join events, created once on the first (non-capturing) call
    static cudaStream_t s2 = nullptr;
    static cudaEvent_t evF = nullptr, evP = nullptr;
    if (!s2) {
        cudaStreamCreateWithFlags(&s2, cudaStreamNonBlocking);
        cudaEventCreateWithFlags(&evF, cudaEventDisableTiming);
        cudaEventCreateWithFlags(&evP, cudaEventDisableTiming);
    }

    // pre-loop: edges/degrees, constants, layer-0 CSR, layer-0 rank-1 "GEMM"
    k_zerodeg<<<(NPAD + 255) / 256, 256>>>();
    k_init<<<512, 256>>>(ei);
    k_prep<<<10, 128>>>(bn_g, bn_b, bn_m, bn_v, pool_p);
    k_tilesum<<<NT[0], 256>>>(0, NS[0], NT[0]);
    k_offsets<<<NT[0], 256>>>(NS[0]);
    k_csrfill<<<256, 256>>>(0, 0);
    k_rank1<<<1024, 256>>>(x, W1, V1, NS[0]);

    for (int L = 0; L < 10; L++) {
        int n = NS[L], k = KS[L];
        int eb = L & 1;
        int gN = (n + 255) / 256;
        int rb = (k + 63) / 64;

        if (L > 0) cudaStreamWaitEvent(0, evP, 0);   // CSR(L) ready

        k_aggtopk<<<gN, 256>>>(L, n, (unsigned)k, gN, conv_b + (size_t)L * D,
                               prelu_a, pool_p + (size_t)L * D);

        // fork: side chain (reads reduce + edge remap, next-layer CSR prep)
        cudaEventRecord(evF, 0);
        cudaStreamWaitEvent(s2, evF, 0);
        if (L < 9) {
            k_side1<<<rb + 256, 128, 0, s2>>>(L, k, eb, 1.0f / (float)k, rb);
            k_tilesum<<<NT[L + 1], 256, 0, s2>>>(L + 1, k, NT[L + 1]);
            k_offsets<<<NT[L + 1], 256, 0, s2>>>(k);
            k_csrfill<<<256, 256, 0, s2>>>(L + 1, eb ^ 1);
        } else {
            k_side1<<<rb, 128, 0, s2>>>(L, k, eb, 1.0f / (float)k, rb);
        }
        cudaEventRecord(evP, s2);

        // main: next layer's GEMM reads pooled rows via g_sel/g_score indirection
        if (L < 9)
            k_gemm2<<<dim3((k + 127) / 128, 2), 256>>>(Ws + (size_t)L * D * D,
                                                       Vs + (size_t)L * D * D, k);
    }

    cudaStreamWaitEvent(0, evP, 0);   // reads(9) complete
    k_lin1<<<dim3(5, 8), 256>>>(lin1_w);
    k_lin2<<<1, 256>>>(lin1_b, lin2_w, lin2_b, prelu_a, out);

    (void)in_sizes; (void)n_in; (void)out_size;
}

// round 16
// speedup vs baseline: 1.6392x; 1.6392x over previous
#include <cuda_runtime.h>
#include <math.h>

#define D 128
#define E_TOTAL 640000
#define NMAX 40000
#define NPAD (NMAX + 1024)

static const int NS[10] = {40000,32000,25600,20480,16384,13108,10487,8390,6712,5370};
static const int KS[10] = {32000,25600,20480,16384,13108,10487,8390,6712,5370,4296};
static const int NT[10] = {40,32,25,20,16,13,11,9,7,6};  // (NS+1023)/1024

// ---------------- device scratch ----------------
__device__ float g_h2 [NMAX*D];
__device__ float g_hw [NMAX*D];
__device__ float g_hv [NMAX*D];
__device__ float g_score[NMAX];
__device__ float g_dinv [NMAX];
__device__ __align__(16) int g_degi[NPAD];
__device__ int   g_remap[NMAX];
__device__ int   g_sel  [NMAX];
__device__ int   g_off  [NMAX+1];
__device__ int   g_cur  [NMAX];
__device__ int   g_csr  [E_TOTAL];
__device__ int2  g_edges[2][E_TOTAL];
__device__ int   g_ecnt[11];
__device__ int   g_tilesum[64];
__device__ int   g_tilepref[64];
__device__ unsigned g_hist[3][65536];   // zero at load; k_topk restores zeros after use
__device__ unsigned g_coarse[3][1024];
__device__ unsigned g_selcnt;
__device__ unsigned g_doneB;
__device__ unsigned g_doneC;
__device__ unsigned g_barArr;
__device__ volatile unsigned g_barGen;
__device__ unsigned g_umax[D];
__device__ float g_colsum[D];
__device__ float g_reads[2560];
__device__ float g_z1[1280];
__device__ float g_bnsc[10*D];
__device__ float g_bnsh[10*D];
__device__ float g_pnorm[10];

// ---------------- helpers ----------------
__device__ __forceinline__ unsigned fmap(float f) {
    unsigned b = __float_as_uint(f);
    return (b & 0x80000000u) ? ~b : (b | 0x80000000u);
}
__device__ __forceinline__ float funmap(unsigned u) {
    unsigned b = (u & 0x80000000u) ? (u ^ 0x80000000u) : ~u;
    return __uint_as_float(b);
}
// 48-bit key: score (32) | inverted index (16). larger == better; ties -> smaller index.
__device__ __forceinline__ unsigned long long make_key(float s, int i) {
    return (((unsigned long long)fmap(s)) << 16) | (unsigned)(0xFFFFu - (unsigned)i);
}

__device__ __forceinline__ void mma_tf32(float* c, const unsigned* a, unsigned b0, unsigned b1) {
    asm volatile(
        "mma.sync.aligned.m16n8k8.row.col.f32.tf32.tf32.f32 "
        "{%0,%1,%2,%3}, {%4,%5,%6,%7}, {%8,%9}, {%0,%1,%2,%3};\n"
        : "+f"(c[0]), "+f"(c[1]), "+f"(c[2]), "+f"(c[3])
        : "r"(a[0]), "r"(a[1]), "r"(a[2]), "r"(a[3]), "r"(b0), "r"(b1));
}

// grid barrier: safe only when ALL nb blocks are resident (single wave). Used ONLY
// by k_topk, which runs alone on the device.
__device__ __forceinline__ void gridbar(unsigned nb) {
    __syncthreads();
    if (threadIdx.x == 0) {
        __threadfence();
        unsigned gen = g_barGen;
        if (atomicAdd(&g_barArr, 1u) == nb - 1) {
            g_barArr = 0;
            __threadfence();
            g_barGen = gen + 1;
        } else {
            while (g_barGen == gen) __nanosleep(64);
            __threadfence();
        }
    }
    __syncthreads();
}

// ---------------- init ----------------
__global__ void k_zerodeg() {
    int gid = blockIdx.x * blockDim.x + threadIdx.x;
    if (gid < NPAD) g_degi[gid] = 0;
}

__global__ void k_init(const int* __restrict__ ei) {
    int gid = blockIdx.x * blockDim.x + threadIdx.x;
    int stride = gridDim.x * blockDim.x;
    for (int i = gid; i < E_TOTAL; i += stride) {
        int d = ei[E_TOTAL + i];
        g_edges[0][i] = make_int2(ei[i], d);
        atomicAdd(&g_degi[d], 1);
    }
    if (gid == 0) g_ecnt[0] = E_TOTAL;
}

// fused BN-const precompute + pool-vector norms + z1 zero: grid 10, block 128
__global__ void k_prep(const float* __restrict__ gamma, const float* __restrict__ beta,
                       const float* __restrict__ mean, const float* __restrict__ var,
                       const float* __restrict__ p) {
    int L = blockIdx.x;
    int t = threadIdx.x;
    int idx = L * 128 + t;
    float sc = gamma[idx] / sqrtf(var[idx] + 1e-5f);
    g_bnsc[idx] = sc;
    g_bnsh[idx] = beta[idx] - mean[idx] * sc;
    g_z1[idx] = 0.f;
    __shared__ float sm[128];
    float v = p[idx];
    sm[t] = v * v;
    __syncthreads();
    for (int s = 64; s > 0; s >>= 1) {
        if (t < s) sm[t] += sm[t + s];
        __syncthreads();
    }
    if (t == 0) g_pnorm[L] = sqrtf(sm[0]);
}

// ---------------- side-stream chain ----------------
// merged: blocks [0, rb) do column max/sum -> g_reads; blocks [rb, ..) remap+compact edges
__global__ void __launch_bounds__(128) k_side1(int L, int k, int ebuf, float invk, int rb) {
    int c = threadIdx.x;
    if ((int)blockIdx.x < rb) {
        // ---- reads reduce ----
        int r0 = blockIdx.x * 64;
        float lmax = __int_as_float(0xff800000);
        float lsum = 0.f;
        int rend = r0 + 64; if (rend > k) rend = k;
        for (int r = r0; r < rend; r++) {
            int i = g_sel[r];
            float v = g_h2[(size_t)i * 128 + c] * g_score[i];
            lmax = fmaxf(lmax, v);
            lsum += v;
        }
        atomicMax(&g_umax[c], fmap(lmax));
        atomicAdd(&g_colsum[c], lsum);
        __threadfence();
        __shared__ int lastb;
        if (c == 0) {
            unsigned v = atomicAdd(&g_doneB, 1u);
            lastb = (v == (unsigned)rb - 1);
            if (lastb) g_doneB = 0u;
        }
        __syncthreads();
        if (lastb) {
            g_reads[L * 256 + c] = funmap(g_umax[c]);
            g_reads[L * 256 + 128 + c] = g_colsum[c] * invk;
        }
    } else {
        // ---- edge remap + compaction + next-layer degrees (warp-aggregated) ----
        int bid = blockIdx.x - rb;
        int gid = bid * 128 + c;
        int stride = ((int)gridDim.x - rb) * 128;
        int lane = c & 31;
        int cnt = g_ecnt[L];
        const int2* Ein = g_edges[ebuf];
        int2* Eout = g_edges[ebuf ^ 1];
        int iters = (cnt + stride - 1) / stride;
        for (int it = 0; it < iters; it++) {
            int i = gid + it * stride;
            int ns = -1, nd = -1;
            if (i < cnt) {
                int2 e = Ein[i];
                ns = g_remap[e.x];
                nd = g_remap[e.y];
            }
            bool keep = (ns >= 0) && (nd >= 0);
            unsigned bm = __ballot_sync(0xFFFFFFFFu, keep);
            if (keep) {
                int leader = __ffs(bm) - 1;
                unsigned base;
                if (lane == leader) base = (unsigned)atomicAdd(&g_ecnt[L + 1], __popc(bm));
                base = __shfl_sync(bm, base, leader);
                unsigned pos = base + __popc(bm & ((1u << lane) - 1u));
                Eout[pos] = make_int2(ns, nd);
                atomicAdd(&g_degi[nd], 1);
            }
        }
    }
}

// tile degree sums + per-layer scalar zeroing; last block computes tile prefix.
__global__ void __launch_bounds__(256) k_tilesum(int L, int n, int ntiles) {
    int t = threadIdx.x;
    int bid = blockIdx.x;
    int gid = bid * 256 + t;
    if (gid < 128) { g_umax[gid] = 0u; g_colsum[gid] = 0.f; }
    if (gid == 0) { g_selcnt = 0u; g_ecnt[L + 1] = 0; }

    int base = bid * 1024 + t * 4;
    int4 dv = *(const int4*)&g_degi[base];
    int s = 0;
    if (base + 0 < n) s += dv.x;
    if (base + 1 < n) s += dv.y;
    if (base + 2 < n) s += dv.z;
    if (base + 3 < n) s += dv.w;
#pragma unroll
    for (int off = 16; off > 0; off >>= 1) s += __shfl_xor_sync(0xFFFFFFFFu, s, off);
    __shared__ int ws[8];
    if ((t & 31) == 0) ws[t >> 5] = s;
    __syncthreads();
    if (t == 0) {
        int tot = 0;
#pragma unroll
        for (int j = 0; j < 8; j++) tot += ws[j];
        g_tilesum[bid] = tot;
    }
    __threadfence();
    __shared__ int lastb;
    if (t == 0) {
        unsigned v = atomicAdd(&g_doneC, 1u);
        lastb = (v == (unsigned)ntiles - 1);
        if (lastb) g_doneC = 0u;
    }
    __syncthreads();
    if (lastb && t == 0) {
        int run = 0;
        for (int i = 0; i < ntiles; i++) { g_tilepref[i] = run; run += g_tilesum[i]; }
        g_off[n] = run;
    }
}

// expand per-tile offsets: one block per 1024-node tile
__global__ void __launch_bounds__(256) k_offsets(int n) {
    int t = threadIdx.x;
    int base = blockIdx.x * 1024 + t * 4;
    int4 dv = *(const int4*)&g_degi[base];
    int d0 = (base + 0 < n) ? dv.x : 0;
    int d1 = (base + 1 < n) ? dv.y : 0;
    int d2 = (base + 2 < n) ? dv.z : 0;
    int d3 = (base + 3 < n) ? dv.w : 0;
    int s = d0 + d1 + d2 + d3;
    int lane = t & 31, wid = t >> 5;
    int incl = s;
#pragma unroll
    for (int off = 1; off < 32; off <<= 1) {
        int v = __shfl_up_sync(0xFFFFFFFFu, incl, off);
        if (lane >= off) incl += v;
    }
    __shared__ int wsum[8], wpref[8];
    if (lane == 31) wsum[wid] = incl;
    __syncthreads();
    if (t < 8) {
        int pp = 0;
#pragma unroll
        for (int j = 0; j < 8; j++) {
            int u = wsum[j];
            if (j < t) pp += u;
        }
        wpref[t] = pp;
    }
    __syncthreads();
    int excl = incl - s + wpref[wid] + g_tilepref[blockIdx.x];
    int dd[4] = {d0, d1, d2, d3};
#pragma unroll
    for (int j = 0; j < 4; j++) {
        int idx = base + j;
        if (idx < n) {
            g_off[idx] = excl;
            g_cur[idx] = excl;
            g_dinv[idx] = (dd[j] > 0) ? (1.0f / sqrtf((float)dd[j])) : 0.f;
            excl += dd[j];
        }
    }
}

// CSR fill: 1 atomic per edge, grid-stride (addresses mostly distinct)
__global__ void k_csrfill(int L, int ebuf) {
    int gid = blockIdx.x * blockDim.x + threadIdx.x;
    int stride = gridDim.x * blockDim.x;
    int cnt = g_ecnt[L];
    const int2* E = g_edges[ebuf];
    for (int i = gid; i < cnt; i += stride) {
        int2 e = E[i];
        int pos = atomicAdd(&g_cur[e.y], 1);
        g_csr[pos] = e.x;
    }
}

// layer 0: hw = x * W1, hv = x * V1
__global__ void k_rank1(const float* __restrict__ x, const float* __restrict__ w,
                        const float* __restrict__ v, int n) {
    int gid = blockIdx.x * blockDim.x + threadIdx.x;
    int stride = gridDim.x * blockDim.x;
    const float4* w4 = (const float4*)w;
    const float4* v4 = (const float4*)v;
    float4* ow = (float4*)g_hw;
    float4* ov = (float4*)g_hv;
    for (int i = gid; i < n * 32; i += stride) {
        float xv = x[i >> 5];
        float4 wv = w4[i & 31];
        float4 vv = v4[i & 31];
        ow[i] = make_float4(xv * wv.x, xv * wv.y, xv * wv.z, xv * wv.w);
        ov[i] = make_float4(xv * vv.x, xv * vv.y, xv * vv.z, xv * vv.w);
    }
}

// agg (warp per node, register acc, unroll-4) + fused conv epilogue + BN + PReLU + score
__global__ void k_aggepi(int L, int n, const float* __restrict__ convb,
                         const float* __restrict__ pa, const float* __restrict__ p) {
    int gid = blockIdx.x * blockDim.x + threadIdx.x;
    int node = gid >> 5;
    int lane = gid & 31;
    if (node >= n) return;
    int st = g_off[node], en = g_off[node + 1];
    float dd = g_dinv[node];
    float4 acc = make_float4(0.f, 0.f, 0.f, 0.f);
    const float4* hw4 = (const float4*)g_hw;
    int j = st;
    for (; j + 4 <= en; j += 4) {           // unroll-4: MLP for the L2 gather
        int s0 = g_csr[j], s1 = g_csr[j + 1], s2 = g_csr[j + 2], s3 = g_csr[j + 3];
        float c0 = g_dinv[s0] * dd, c1 = g_dinv[s1] * dd;
        float c2 = g_dinv[s2] * dd, c3 = g_dinv[s3] * dd;
        float4 v0 = hw4[(size_t)s0 * 32 + lane];
        float4 v1 = hw4[(size_t)s1 * 32 + lane];
        float4 v2 = hw4[(size_t)s2 * 32 + lane];
        float4 v3 = hw4[(size_t)s3 * 32 + lane];
        acc.x += v0.x * c0 + v1.x * c1 + v2.x * c2 + v3.x * c3;
        acc.y += v0.y * c0 + v1.y * c1 + v2.y * c2 + v3.y * c3;
        acc.z += v0.z * c0 + v1.z * c1 + v2.z * c2 + v3.z * c3;
        acc.w += v0.w * c0 + v1.w * c1 + v2.w * c2 + v3.w * c3;
    }
    for (; j < en; j++) {
        int s = g_csr[j];
        float c = g_dinv[s] * dd;
        float4 v = hw4[(size_t)s * 32 + lane];
        acc.x += v.x * c; acc.y += v.y * c; acc.z += v.z * c; acc.w += v.w * c;
    }
    float a = pa[0];
    float4 hv = ((const float4*)g_hv)[(size_t)node * 32 + lane];
    float4 cb = ((const float4*)convb)[lane];
    float4 s4 = ((const float4*)(g_bnsc + L * 128))[lane];
    float4 h4 = ((const float4*)(g_bnsh + L * 128))[lane];
    float4 p4 = ((const float4*)p)[lane];
    float o[4] = {acc.x + hv.x + cb.x, acc.y + hv.y + cb.y,
                  acc.z + hv.z + cb.z, acc.w + hv.w + cb.w};
    float bs[4] = {s4.x, s4.y, s4.z, s4.w};
    float bh[4] = {h4.x, h4.y, h4.z, h4.w};
    float pv[4] = {p4.x, p4.y, p4.z, p4.w};
    float sp = 0.f;
#pragma unroll
    for (int q = 0; q < 4; q++) {
        float v = fmaxf(o[q], 0.f);
        v = v * bs[q] + bh[q];
        v = v > 0.f ? v : a * v;
        o[q] = v;
        sp += v * pv[q];
    }
    ((float4*)g_h2)[(size_t)node * 32 + lane] = make_float4(o[0], o[1], o[2], o[3]);
#pragma unroll
    for (int off = 16; off > 0; off >>= 1) sp += __shfl_xor_sync(0xFFFFFFFFu, sp, off);
    if (lane == 0) g_score[node] = tanhf(sp / g_pnorm[L]);
}

// ---------------- TF32 tensor-core GEMM with indirect pooled A ----------------
// A row r = g_h2[g_sel[r]] * g_score[g_sel[r]]   (pooled output of previous layer)
#define GBK 16
__global__ void __launch_bounds__(256) k_gemm2(const float* __restrict__ W,
                                               const float* __restrict__ V, int n) {
    __shared__ float Ah[GBK][136], Al[GBK][136];
    __shared__ float Bh[GBK][136], Bl[GBK][136];
    const float* B = blockIdx.y ? V : W;
    float* out = blockIdx.y ? g_hv : g_hw;
    int tid = threadIdx.x;
    int lane = tid & 31;
    int warp = tid >> 5;
    int wm = warp >> 2;
    int wn = warp & 3;
    int group = lane >> 2;
    int tig = lane & 3;
    int row0 = blockIdx.x * 128;

    float acc[4][4][4];
#pragma unroll
    for (int mt = 0; mt < 4; mt++)
#pragma unroll
        for (int nt = 0; nt < 4; nt++)
#pragma unroll
            for (int e = 0; e < 4; e++) acc[mt][nt][e] = 0.f;

    for (int k0 = 0; k0 < 128; k0 += GBK) {
#pragma unroll
        for (int q = 0; q < 2; q++) {
            int f = tid + 256 * q;
            int m = f >> 2;
            int kq = (f & 3) * 4;
            int gr = row0 + m; if (gr >= n) gr = n - 1;
            int src = g_sel[gr];
            float sc = g_score[src];
            float4 v = *(const float4*)(g_h2 + (size_t)src * 128 + k0 + kq);
            float xs[4] = {v.x * sc, v.y * sc, v.z * sc, v.w * sc};
#pragma unroll
            for (int j = 0; j < 4; j++) {
                float xv = xs[j];
                float hf = __uint_as_float(__float_as_uint(xv) & 0xFFFFE000u);
                Ah[kq + j][m] = hf;
                Al[kq + j][m] = xv - hf;
            }
        }
#pragma unroll
        for (int q = 0; q < 2; q++) {
            int f = tid + 256 * q;
            int kk = f >> 5;
            int nq = (f & 31) * 4;
            float4 v = *(const float4*)(B + (size_t)(k0 + kk) * 128 + nq);
            float xs[4] = {v.x, v.y, v.z, v.w};
            float hi[4], lo[4];
#pragma unroll
            for (int j = 0; j < 4; j++) {
                hi[j] = __uint_as_float(__float_as_uint(xs[j]) & 0xFFFFE000u);
                lo[j] = xs[j] - hi[j];
            }
            *(float4*)&Bh[kk][nq] = make_float4(hi[0], hi[1], hi[2], hi[3]);
            *(float4*)&Bl[kk][nq] = make_float4(lo[0], lo[1], lo[2], lo[3]);
        }
        __syncthreads();
#pragma unroll
        for (int ks = 0; ks < GBK; ks += 8) {
            unsigned ah[4][4], al[4][4];
#pragma unroll
            for (int mt = 0; mt < 4; mt++) {
                int m = wm * 64 + mt * 16 + group;
                ah[mt][0] = __float_as_uint(Ah[ks + tig][m]);
                ah[mt][1] = __float_as_uint(Ah[ks + tig][m + 8]);
                ah[mt][2] = __float_as_uint(Ah[ks + tig + 4][m]);
                ah[mt][3] = __float_as_uint(Ah[ks + tig + 4][m + 8]);
                al[mt][0] = __float_as_uint(Al[ks + tig][m]);
                al[mt][1] = __float_as_uint(Al[ks + tig][m + 8]);
                al[mt][2] = __float_as_uint(Al[ks + tig + 4][m]);
                al[mt][3] = __float_as_uint(Al[ks + tig + 4][m + 8]);
            }
#pragma unroll
            for (int nt = 0; nt < 4; nt++) {
                int c = wn * 32 + nt * 8 + group;
                unsigned bh0 = __float_as_uint(Bh[ks + tig][c]);
                unsigned bh1 = __float_as_uint(Bh[ks + tig + 4][c]);
                unsigned bl0 = __float_as_uint(Bl[ks + tig][c]);
                unsigned bl1 = __float_as_uint(Bl[ks + tig + 4][c]);
#pragma unroll
                for (int mt = 0; mt < 4; mt++) {
                    mma_tf32(acc[mt][nt], ah[mt], bh0, bh1);
                    mma_tf32(acc[mt][nt], ah[mt], bl0, bl1);
                    mma_tf32(acc[mt][nt], al[mt], bh0, bh1);
                }
            }
        }
        __syncthreads();
    }

#pragma unroll
    for (int mt = 0; mt < 4; mt++) {
#pragma unroll
        for (int h = 0; h < 2; h++) {
            int r = row0 + wm * 64 + mt * 16 + group + 8 * h;
            if (r >= n) continue;
#pragma unroll
            for (int nt = 0; nt < 4; nt++) {
                int cb = wn * 32 + nt * 8 + tig * 2;
                *(float2*)(out + (size_t)r * 128 + cb) =
                    make_float2(acc[mt][nt][2 * h], acc[mt][nt][2 * h + 1]);
            }
        }
    }
}

// ---------------- top-k: 3 radix passes, warp-aggregated atomics, light scan ----------------
__device__ __forceinline__ void scan_pass(int pass, unsigned kr_in, unsigned* kr_out,
                                          unsigned long long* prefix, int shift) {
    __shared__ unsigned sh[256];
    __shared__ unsigned wtot[8];
    __shared__ unsigned sh_dig, sh_kr;
    int t = threadIdx.x;
    int lane = t & 31, wid = t >> 5;
    int cb0 = t * 4;
    unsigned s = 0;
#pragma unroll
    for (int q = 0; q < 4; q++) s += g_coarse[pass][cb0 + q];
    sh[t] = s;
    __syncthreads();
    unsigned incl = sh[255 - t];
#pragma unroll
    for (int off = 1; off < 32; off <<= 1) {
        unsigned u = __shfl_up_sync(0xFFFFFFFFu, incl, off);
        if (lane >= off) incl += u;
    }
    if (lane == 31) wtot[wid] = incl;
    __syncthreads();
    unsigned woff = 0;
#pragma unroll
    for (int j = 0; j < 8; j++)
        if (j < wid) woff += wtot[j];
    sh[t] = incl + woff;          // inclusive scan of reversed chunk sums
    __syncthreads();
    unsigned suf = sh[255 - t];   // suffix sum incl. own chunk
    unsigned above = suf - s;
    if (above < kr_in && suf >= kr_in) {   // exactly one thread
        unsigned running = above;
        for (int b = 3; b >= 0; b--) {
            unsigned c = g_coarse[pass][cb0 + b];
            if (running + c >= kr_in) {
                int fb = (cb0 + b) * 64;
                for (int d = 63; d >= 0; d--) {
                    unsigned fc = g_hist[pass][fb + d];
                    if (running + fc >= kr_in) {
                        sh_kr = kr_in - running;
                        sh_dig = (unsigned)(fb + d);
                        break;
                    }
                    running += fc;
                }
                break;
            }
            running += c;
        }
    }
    __syncthreads();
    *prefix |= ((unsigned long long)sh_dig) << shift;
    *kr_out = sh_kr;
    __syncthreads();  // protect shared reuse next pass
}

__global__ void __launch_bounds__(256) k_topk(int n, unsigned k, int nb) {
    int t = threadIdx.x;
    int lane = t & 31;
    int i = blockIdx.x * 256 + t;
    bool valid = (i < n);
    unsigned long long key = valid ? make_key(g_score[i], i) : 0ull;
    unsigned long long prefix = 0;
    unsigned kr = k;
    unsigned digits[3];
    int actmask = 0;
#pragma unroll
    for (int pass = 0; pass < 3; pass++) {
        int shift = 32 - 16 * pass;
        bool act = valid && (pass == 0 || ((key >> (shift + 16)) == (prefix >> (shift + 16))));
        unsigned digit = (unsigned)((key >> shift) & 0xFFFFull);
        unsigned am = __ballot_sync(0xFFFFFFFFu, act);
        if (act) {
            digits[pass] = digit;
            actmask |= 1 << pass;
            // warp-aggregate equal digits (saturated scores concentrate in one bin)
            unsigned peers = __match_any_sync(am, digit);
            if (lane == (__ffs(peers) - 1)) {
                unsigned cnt = (unsigned)__popc(peers);
                atomicAdd(&g_hist[pass][digit], cnt);
                atomicAdd(&g_coarse[pass][digit >> 6], cnt);
            }
        }
        gridbar((unsigned)nb);
        scan_pass(pass, kr, &kr, &prefix, shift);
    }
    gridbar((unsigned)nb);  // all scans done before clearing
    // clear touched bins (leaders only; plain stores)
#pragma unroll
    for (int pass = 0; pass < 3; pass++) {
        bool a = (actmask >> pass) & 1;
        unsigned am = __ballot_sync(0xFFFFFFFFu, a);
        if (a) {
            unsigned peers = __match_any_sync(am, digits[pass]);
            if (lane == (__ffs(peers) - 1)) {
                g_hist[pass][digits[pass]] = 0u;
                g_coarse[pass][digits[pass] >> 6] = 0u;
            }
        }
    }
    if (valid) g_degi[i] = 0;  // degrees consumed; clear for next layer
    bool sel = valid && (key >= prefix);
    unsigned bm = __ballot_sync(0xFFFFFFFFu, sel);
    if (sel) {
        int leader = __ffs(bm) - 1;
        unsigned base;
        if (lane == leader) base = atomicAdd(&g_selcnt, (unsigned)__popc(bm));
        base = __shfl_sync(bm, base, leader);
        unsigned pos = base + __popc(bm & ((1u << lane) - 1u));
        g_sel[pos] = i;
        g_remap[i] = (int)pos;
    } else if (valid) {
        g_remap[i] = -1;
    }
}

// ---------------- MLP head ----------------
__global__ void k_lin1(const float* __restrict__ W) {
    int col = blockIdx.x * 256 + threadIdx.x;
    int r0 = blockIdx.y * 320;
    float acc = 0.f;
    for (int r = r0; r < r0 + 320; r++) acc += g_reads[r] * W[(size_t)r * 1280 + col];
    atomicAdd(&g_z1[col], acc);
}

__global__ void k_lin2(const float* __restrict__ b1, const float* __restrict__ W2,
                       const float* __restrict__ b2, const float* __restrict__ pa,
                       float* __restrict__ out) {
    int tid = threadIdx.x;
    float a = pa[0];
    float acc[8] = {0, 0, 0, 0, 0, 0, 0, 0};
    for (int i = tid; i < 1280; i += 256) {
        float v = g_z1[i] + b1[i];
        v = v > 0.f ? v : a * v;
#pragma unroll
        for (int j = 0; j < 8; j++) acc[j] += v * W2[i * 8 + j];
    }
    __shared__ float red[256][8];
#pragma unroll
    for (int j = 0; j < 8; j++) red[tid][j] = acc[j];
    __syncthreads();
    for (int s = 128; s > 0; s >>= 1) {
        if (tid < s)
#pragma unroll
            for (int j = 0; j < 8; j++) red[tid][j] += red[tid + s][j];
        __syncthreads();
    }
    if (tid == 0) {
        float z[8];
#pragma unroll
        for (int j = 0; j < 8; j++) {
            float s = red[0][j] + b2[j];
            z[j] = s > 0.f ? s : a * s;
        }
        float mn = z[0];
#pragma unroll
        for (int j = 1; j < 8; j++) mn = fminf(mn, z[j]);
#pragma unroll
        for (int j = 0; j < 8; j++) z[j] -= mn;
        float mx = z[0];
#pragma unroll
        for (int j = 1; j < 8; j++) mx = fmaxf(mx, z[j]);
#pragma unroll
        for (int j = 0; j < 8; j++) z[j] /= mx;
        float sm = 0.f;
#pragma unroll
        for (int j = 0; j < 8; j++) sm += z[j];
#pragma unroll
        for (int j = 0; j < 8; j++) out[j] = z[j] / sm;
    }
}

// ---------------- launcher ----------------
extern "C" void kernel_launch(void* const* d_in, const int* in_sizes, int n_in,
                              void* d_out, int out_size) {
    const float* x       = (const float*)d_in[0];
    const int*   ei      = (const int*)  d_in[1];
    const float* W1      = (const float*)d_in[2];
    const float* V1      = (const float*)d_in[3];
    const float* Ws      = (const float*)d_in[4];
    const float* Vs      = (const float*)d_in[5];
    const float* conv_b  = (const float*)d_in[6];
    const float* bn_g    = (const float*)d_in[7];
    const float* bn_b    = (const float*)d_in[8];
    const float* bn_m    = (const float*)d_in[9];
    const float* bn_v    = (const float*)d_in[10];
    const float* pool_p  = (const float*)d_in[11];
    const float* prelu_a = (const float*)d_in[12];
    const float* lin1_w  = (const float*)d_in[13];
    const float* lin1_b  = (const float*)d_in[14];
    const float* lin2_w  = (const float*)d_in[15];
    const float* lin2_b  = (const float*)d_in[16];
    float* out = (float*)d_out;

    // side stream + fork/join events, created once on the first (non-capturing) call
    static cudaStream_t s2 = nullptr;
    static cudaEvent_t evF = nullptr, evP = nullptr;
    if (!s2) {
        cudaStreamCreateWithFlags(&s2, cudaStreamNonBlocking);
        cudaEventCreateWithFlags(&evF, cudaEventDisableTiming);
        cudaEventCreateWithFlags(&evP, cudaEventDisableTiming);
    }

    // pre-loop: edges/degrees, constants, layer-0 CSR, layer-0 rank-1 "GEMM"
    k_zerodeg<<<(NPAD + 255) / 256, 256>>>();
    k_init<<<512, 256>>>(ei);
    k_prep<<<10, 128>>>(bn_g, bn_b, bn_m, bn_v, pool_p);
    k_tilesum<<<NT[0], 256>>>(0, NS[0], NT[0]);
    k_offsets<<<NT[0], 256>>>(NS[0]);
    k_csrfill<<<256, 256>>>(0, 0);
    k_rank1<<<1024, 256>>>(x, W1, V1, NS[0]);

    for (int L = 0; L < 10; L++) {
        int n = NS[L], k = KS[L];
        int eb = L & 1;
        int gN = (n + 255) / 256;
        int rb = (k + 63) / 64;

        if (L > 0) cudaStreamWaitEvent(0, evP, 0);   // CSR(L) ready

        k_aggepi<<<(n * 32 + 255) / 256, 256>>>(L, n, conv_b + (size_t)L * D,
                                                prelu_a, pool_p + (size_t)L * D);

        k_topk<<<gN, 256>>>(n, (unsigned)k, gN);

        // fork: side chain (reads reduce + edge remap, next-layer CSR prep)
        cudaEventRecord(evF, 0);
        cudaStreamWaitEvent(s2, evF, 0);
        if (L < 9) {
            k_side1<<<rb + 256, 128, 0, s2>>>(L, k, eb, 1.0f / (float)k, rb);
            k_tilesum<<<NT[L + 1], 256, 0, s2>>>(L + 1, k, NT[L + 1]);
            k_offsets<<<NT[L + 1], 256, 0, s2>>>(k);
            k_csrfill<<<256, 256, 0, s2>>>(L + 1, eb ^ 1);
        } else {
            k_side1<<<rb, 128, 0, s2>>>(L, k, eb, 1.0f / (float)k, rb);
        }
        cudaEventRecord(evP, s2);

        // main: next layer's GEMM reads pooled rows via g_sel/g_score indirection
        if (L < 9)
            k_gemm2<<<dim3((k + 127) / 128, 2), 256>>>(Ws + (size_t)L * D * D,
                                                       Vs + (size_t)L * D * D, k);
    }

    cudaStreamWaitEvent(0, evP, 0);   // reads(9) complete
    k_lin1<<<dim3(5, 8), 256>>>(lin1_w);
    k_lin2<<<1, 256>>>(lin1_b, lin2_w, lin2_b, prelu_a, out);

    (void)in_sizes; (void)n_in; (void)out_size;
}